// round 16
// baseline (speedup 1.0000x reference)
#include <cuda_runtime.h>
#include <cuda_fp16.h>
#include <math.h>

#define NQ    128
#define ED    256
#define DFFD  512
#define CAMSN 6
#define TSTEP 2
#define CFCH  256
#define HGT   64
#define WID   160
#define PLANE (HGT*WID)           /* 10240 */
#define NPTS  150
#define NTAPS (NPTS*CAMSN*TSTEP)  /* 1800 */
#define NB    128
#define NT    512

// ---------------- device scratch ----------------
__device__ float  g_q    [NQ*ED];
__device__ float  g_h    [NQ*DFFD];
__device__ float  g_mem  [NQ*ED];
__device__ float  g_qh   [NQ*ED];
__device__ float  g_kT   [ED*NQ];     // transposed K: [256 dims][128 queries]
__device__ float  g_vh   [NQ*ED];
__device__ __align__(16) unsigned char g_feat8[(size_t)CAMSN*TSTEP*PLANE*CFCH]; // 31.5 MB fp8 pixel-major

// transposed matvec weights, fp16: WT[k][c]
__device__ __align__(16) __half g_fmw1T[256*512];
__device__ __align__(16) __half g_fmw2T[512*256];
__device__ __align__(16) __half g_l1wT [6*256*512];
__device__ __align__(16) __half g_l2wT [6*512*256];
__device__ __align__(16) __half g_saowT[6*256*256];
__device__ __align__(16) __half g_caowT[6*256*256];

__device__ unsigned g_bar_arrive;
__device__ unsigned g_bar_gen;

// ---------------- shared memory union ----------------
struct SmemGemm   { float As[2][32][20]; float Ws[2][32][68]; };   // 22528 B
struct SmemGemm2  { SmemGemm h[2]; };                              // 45056 B
struct SmemS2 {                       // per-query stage scratch
    uint4  w[NTAPS];                  // 28800 B (sampling weights; reused as reduce buf)
    int    row[NTAPS];                // 7200 B (contiguous after w; reduce buf spills here when dead)
    float  agg[256];
    float  h[512];
    float  tp[11];
    float  cs[2];
    float  ctc[12][14];
};
struct SmemAttn {
    float  q[256];
    float  Ps[8*128];
    float  mxp[16];
    float  sump[16];
    float  ovp[256];
    float  ao[256];
    float  tmpv[256];
    float  red[16];
    float4 pbuf[960];                 // matvec partials
};
struct SmemTrans  { float tile[32][33]; };
union __align__(16) Smem {
    SmemGemm2  g2;
    SmemS2     s;
    SmemAttn   a;
    SmemTrans  t;
};

// ---------------- fp8 converts ----------------
__device__ __forceinline__ __half2 cvt8(unsigned short v)
{
    unsigned r;
    asm("cvt.rn.f16x2.e4m3x2 %0, %1;" : "=r"(r) : "h"(v));
    return *(__half2*)&r;
}
__device__ __forceinline__ unsigned short pack8(float hi, float lo)
{
    unsigned short r;
    asm("cvt.rn.satfinite.e4m3x2.f32 %0, %1, %2;" : "=h"(r) : "f"(hi), "f"(lo));
    return r;
}

// ---------------- named barrier for 256-thread half-CTA ----------------
__device__ __forceinline__ void half_bar(int id)
{
    asm volatile("bar.sync %0, 256;" :: "r"(id) : "memory");
}

// ---------------- software grid barrier: release/acquire, replay-safe ----------------
__device__ __forceinline__ void grid_sync(unsigned bar0, unsigned& cnt)
{
    __syncthreads();
    cnt++;
    if (threadIdx.x == 0) {
        unsigned target = bar0 + cnt;
        unsigned t;
        asm volatile("atom.release.gpu.global.add.u32 %0, [%1], 1;"
                     : "=r"(t) : "l"(&g_bar_arrive) : "memory");
        if (t == (unsigned)(NB - 1)) {
            g_bar_arrive = 0u;
            asm volatile("st.release.gpu.global.u32 [%0], %1;"
                         :: "l"(&g_bar_gen), "r"(target) : "memory");
        } else {
            unsigned cur;
            do {
                asm volatile("ld.acquire.gpu.global.u32 %0, [%1];"
                             : "=r"(cur) : "l"(&g_bar_gen) : "memory");
            } while ((int)(cur - target) < 0);
        }
    }
    __syncthreads();
}

__device__ __forceinline__ float warp_red(float v)
{
    #pragma unroll
    for (int o = 16; o; o >>= 1) v += __shfl_xor_sync(0xffffffffu, v, o);
    return v;
}

__device__ __forceinline__ float dot4(float4 a, float4 b)
{
    return fmaf(a.x, b.x, fmaf(a.y, b.y, fmaf(a.z, b.z, a.w * b.w)));
}

// ---------------- fp32->fp16 transposed weight staging ----------------
__device__ void wtransH(Smem* sm, const float* __restrict__ src, __half* __restrict__ dst,
                        int R, int C)
{
    int t = threadIdx.x;
    int tx = t & 31, ty = t >> 5;     // 32 x 16
    int rt = R >> 5;
    int nt = rt * (C >> 5);
    for (int tile = blockIdx.x; tile < nt; tile += NB) {
        int r0 = (tile % rt) << 5;
        int c0 = (tile / rt) << 5;
        #pragma unroll
        for (int i = 0; i < 32; i += 16)
            sm->t.tile[ty + i][tx] = src[(size_t)(r0 + ty + i) * C + c0 + tx];
        __syncthreads();
        #pragma unroll
        for (int i = 0; i < 32; i += 16)
            dst[(size_t)(c0 + ty + i) * R + r0 + tx] = __float2half_rn(sm->t.tile[tx][ty + i]);
        __syncthreads();
    }
}

// ---------------- one 16x64 GEMM tile on a 256-thread half, dbuf K=32 ----------------
template <int ACT, int QKV>
__device__ void gemm_tile(SmemGemm* sg, int tl, int barid,
                          const float* __restrict__ A,
                          const float* __restrict__ W, const float* __restrict__ Bb,
                          float* __restrict__ C, int K, int ldc, int m0, int n0)
{
    int tx = tl & 15;
    int ty = tl >> 4;
    float acc[4] = {0.f, 0.f, 0.f, 0.f};

#define LOAD_CHUNK(k0, b) do {                                                  \
        if (tl < 128) {                                                         \
            int r = tl >> 3, kq = tl & 7;                                       \
            float4 v = *(const float4*)&A[(m0 + r) * K + (k0) + kq * 4];        \
            sg->As[b][kq*4+0][r] = v.x; sg->As[b][kq*4+1][r] = v.y;             \
            sg->As[b][kq*4+2][r] = v.z; sg->As[b][kq*4+3][r] = v.w;             \
        }                                                                        \
        {                                                                        \
            int r = tl >> 2, kq = tl & 3;                                       \
            float4 v0 = *(const float4*)&W[(n0 + r) * K + (k0) + kq * 4];       \
            float4 v1 = *(const float4*)&W[(n0 + r) * K + (k0) + 16 + kq * 4];  \
            sg->Ws[b][kq*4+0][r] = v0.x; sg->Ws[b][kq*4+1][r] = v0.y;           \
            sg->Ws[b][kq*4+2][r] = v0.z; sg->Ws[b][kq*4+3][r] = v0.w;           \
            sg->Ws[b][16+kq*4+0][r] = v1.x; sg->Ws[b][16+kq*4+1][r] = v1.y;     \
            sg->Ws[b][16+kq*4+2][r] = v1.z; sg->Ws[b][16+kq*4+3][r] = v1.w;     \
        }                                                                        \
    } while (0)

    LOAD_CHUNK(0, 0);
    half_bar(barid);
    int p = 0;
    for (int k0 = 0; k0 < K; k0 += 32) {
        if (k0 + 32 < K) LOAD_CHUNK(k0 + 32, p ^ 1);
        #pragma unroll
        for (int k = 0; k < 32; k++) {
            float a  = sg->As[p][k][ty];
            float4 w = *(const float4*)&sg->Ws[p][k][tx*4];
            acc[0] = fmaf(a, w.x, acc[0]);
            acc[1] = fmaf(a, w.y, acc[1]);
            acc[2] = fmaf(a, w.z, acc[2]);
            acc[3] = fmaf(a, w.w, acc[3]);
        }
        half_bar(barid);
        p ^= 1;
    }
#undef LOAD_CHUNK

    int row = m0 + ty;
    int col = n0 + tx * 4;
    float4 bv = *(const float4*)&Bb[col];
    float4 r;
    r.x = acc[0] + bv.x;
    r.y = acc[1] + bv.y;
    r.z = acc[2] + bv.z;
    r.w = acc[3] + bv.w;
    if (ACT) {
        r.x = fmaxf(r.x, 0.f); r.y = fmaxf(r.y, 0.f);
        r.z = fmaxf(r.z, 0.f); r.w = fmaxf(r.w, 0.f);
    }
    if (QKV) {
        if (col < 256) {
            *(float4*)&g_qh[row * 256 + col] = r;
        } else if (col < 512) {
            int kd = col - 256;
            g_kT[(kd+0)*NQ + row] = r.x;
            g_kT[(kd+1)*NQ + row] = r.y;
            g_kT[(kd+2)*NQ + row] = r.z;
            g_kT[(kd+3)*NQ + row] = r.w;
        } else {
            *(float4*)&g_vh[row * 256 + (col - 512)] = r;
        }
    } else {
        *(float4*)&C[row * ldc + col] = r;
    }
}

// ---------------- fp16-weight split-K matvecs: WT half[k][c] ----------------
__device__ void mvT_256to512_h(const float* __restrict__ xs, const __half* __restrict__ WT,
                               const float* __restrict__ Bb, float* __restrict__ hs,
                               float4* pbuf)
{
    int t = threadIdx.x;
    int oct = t & 63;
    int ks  = t >> 6;               // 0..7
    const uint4* wt = (const uint4*)WT;   // row stride 64 uint4
    float4 a0 = {0.f,0.f,0.f,0.f}, a1 = {0.f,0.f,0.f,0.f};
    int kb = ks * 32;
    #pragma unroll 8
    for (int k = 0; k < 32; k++) {
        float xk = xs[kb + k];
        uint4 w = wt[(size_t)(kb + k) * 64 + oct];
        float2 f0 = __half22float2(*(const __half2*)&w.x);
        float2 f1 = __half22float2(*(const __half2*)&w.y);
        float2 f2 = __half22float2(*(const __half2*)&w.z);
        float2 f3 = __half22float2(*(const __half2*)&w.w);
        a0.x = fmaf(xk, f0.x, a0.x); a0.y = fmaf(xk, f0.y, a0.y);
        a0.z = fmaf(xk, f1.x, a0.z); a0.w = fmaf(xk, f1.y, a0.w);
        a1.x = fmaf(xk, f2.x, a1.x); a1.y = fmaf(xk, f2.y, a1.y);
        a1.z = fmaf(xk, f3.x, a1.z); a1.w = fmaf(xk, f3.y, a1.w);
    }
    if (ks > 0) {
        pbuf[(ks - 1) * 128 + oct * 2 + 0] = a0;
        pbuf[(ks - 1) * 128 + oct * 2 + 1] = a1;
    }
    __syncthreads();
    if (ks == 0) {
        #pragma unroll
        for (int p = 0; p < 7; p++) {
            float4 b0 = pbuf[p * 128 + oct * 2 + 0];
            float4 b1 = pbuf[p * 128 + oct * 2 + 1];
            a0.x += b0.x; a0.y += b0.y; a0.z += b0.z; a0.w += b0.w;
            a1.x += b1.x; a1.y += b1.y; a1.z += b1.z; a1.w += b1.w;
        }
        float4 bb0 = *(const float4*)&Bb[oct * 8];
        float4 bb1 = *(const float4*)&Bb[oct * 8 + 4];
        a0.x = fmaxf(a0.x + bb0.x, 0.f); a0.y = fmaxf(a0.y + bb0.y, 0.f);
        a0.z = fmaxf(a0.z + bb0.z, 0.f); a0.w = fmaxf(a0.w + bb0.w, 0.f);
        a1.x = fmaxf(a1.x + bb1.x, 0.f); a1.y = fmaxf(a1.y + bb1.y, 0.f);
        a1.z = fmaxf(a1.z + bb1.z, 0.f); a1.w = fmaxf(a1.w + bb1.w, 0.f);
        *(float4*)&hs[oct * 8]     = a0;
        *(float4*)&hs[oct * 8 + 4] = a1;
    }
    __syncthreads();
}

__device__ void mvT_512to256_h(const float* __restrict__ xs, const __half* __restrict__ WT,
                               const float* __restrict__ Bb, float* __restrict__ outv,
                               float4* pbuf)
{
    int t = threadIdx.x;
    int oct = t & 31;
    int ks  = t >> 5;               // 0..15
    const uint4* wt = (const uint4*)WT;   // row stride 32 uint4
    float4 a0 = {0.f,0.f,0.f,0.f}, a1 = {0.f,0.f,0.f,0.f};
    int kb = ks * 32;
    #pragma unroll 8
    for (int k = 0; k < 32; k++) {
        float xk = xs[kb + k];
        uint4 w = wt[(size_t)(kb + k) * 32 + oct];
        float2 f0 = __half22float2(*(const __half2*)&w.x);
        float2 f1 = __half22float2(*(const __half2*)&w.y);
        float2 f2 = __half22float2(*(const __half2*)&w.z);
        float2 f3 = __half22float2(*(const __half2*)&w.w);
        a0.x = fmaf(xk, f0.x, a0.x); a0.y = fmaf(xk, f0.y, a0.y);
        a0.z = fmaf(xk, f1.x, a0.z); a0.w = fmaf(xk, f1.y, a0.w);
        a1.x = fmaf(xk, f2.x, a1.x); a1.y = fmaf(xk, f2.y, a1.y);
        a1.z = fmaf(xk, f3.x, a1.z); a1.w = fmaf(xk, f3.y, a1.w);
    }
    if (ks > 0) {
        pbuf[(ks - 1) * 64 + oct * 2 + 0] = a0;
        pbuf[(ks - 1) * 64 + oct * 2 + 1] = a1;
    }
    __syncthreads();
    if (ks == 0) {
        #pragma unroll
        for (int p = 0; p < 15; p++) {
            float4 b0 = pbuf[p * 64 + oct * 2 + 0];
            float4 b1 = pbuf[p * 64 + oct * 2 + 1];
            a0.x += b0.x; a0.y += b0.y; a0.z += b0.z; a0.w += b0.w;
            a1.x += b1.x; a1.y += b1.y; a1.z += b1.z; a1.w += b1.w;
        }
        float4 bb0 = *(const float4*)&Bb[oct * 8];
        float4 bb1 = *(const float4*)&Bb[oct * 8 + 4];
        a0.x += bb0.x; a0.y += bb0.y; a0.z += bb0.z; a0.w += bb0.w;
        a1.x += bb1.x; a1.y += bb1.y; a1.z += bb1.z; a1.w += bb1.w;
        *(float4*)&outv[oct * 8]     = a0;
        *(float4*)&outv[oct * 8 + 4] = a1;
    }
    __syncthreads();
}

__device__ void mvT_256to256_h(const float* __restrict__ xs, const __half* __restrict__ WT,
                               const float* __restrict__ Bb, float* __restrict__ outv,
                               float4* pbuf)
{
    int t = threadIdx.x;
    int oct = t & 31;
    int ks  = t >> 5;               // 0..15
    const uint4* wt = (const uint4*)WT;   // row stride 32 uint4
    float4 a0 = {0.f,0.f,0.f,0.f}, a1 = {0.f,0.f,0.f,0.f};
    int kb = ks * 16;
    #pragma unroll 8
    for (int k = 0; k < 16; k++) {
        float xk = xs[kb + k];
        uint4 w = wt[(size_t)(kb + k) * 32 + oct];
        float2 f0 = __half22float2(*(const __half2*)&w.x);
        float2 f1 = __half22float2(*(const __half2*)&w.y);
        float2 f2 = __half22float2(*(const __half2*)&w.z);
        float2 f3 = __half22float2(*(const __half2*)&w.w);
        a0.x = fmaf(xk, f0.x, a0.x); a0.y = fmaf(xk, f0.y, a0.y);
        a0.z = fmaf(xk, f1.x, a0.z); a0.w = fmaf(xk, f1.y, a0.w);
        a1.x = fmaf(xk, f2.x, a1.x); a1.y = fmaf(xk, f2.y, a1.y);
        a1.z = fmaf(xk, f3.x, a1.z); a1.w = fmaf(xk, f3.y, a1.w);
    }
    if (ks > 0) {
        pbuf[(ks - 1) * 64 + oct * 2 + 0] = a0;
        pbuf[(ks - 1) * 64 + oct * 2 + 1] = a1;
    }
    __syncthreads();
    if (ks == 0) {
        #pragma unroll
        for (int p = 0; p < 15; p++) {
            float4 b0 = pbuf[p * 64 + oct * 2 + 0];
            float4 b1 = pbuf[p * 64 + oct * 2 + 1];
            a0.x += b0.x; a0.y += b0.y; a0.z += b0.z; a0.w += b0.w;
            a1.x += b1.x; a1.y += b1.y; a1.z += b1.z; a1.w += b1.w;
        }
        float4 bb0 = *(const float4*)&Bb[oct * 8];
        float4 bb1 = *(const float4*)&Bb[oct * 8 + 4];
        a0.x += bb0.x; a0.y += bb0.y; a0.z += bb0.z; a0.w += bb0.w;
        a1.x += bb1.x; a1.y += bb1.y; a1.z += bb1.z; a1.w += bb1.w;
        *(float4*)&outv[oct * 8]     = a0;
        *(float4*)&outv[oct * 8 + 4] = a1;
    }
    __syncthreads();
}

// ---------------- residual add + LayerNorm (single-pass mean/var) ----------------
__device__ void resln_inblock(Smem* sm, int m, const float* __restrict__ lng,
                              const float* __restrict__ lnb, float* qsave)
{
    int t = threadIdx.x, lane = t & 31, w = t >> 5;
    float x = 0.f;
    if (t < 256) x = g_q[m * 256 + t] + sm->a.tmpv[t];

    float v1 = x, v2 = x * x;
    #pragma unroll
    for (int o = 16; o; o >>= 1) {
        v1 += __shfl_xor_sync(0xffffffffu, v1, o);
        v2 += __shfl_xor_sync(0xffffffffu, v2, o);
    }
    if (lane == 0) { sm->a.red[w] = v1; sm->a.red[w + 8] = v2; }
    __syncthreads();
    float s1 = 0.f, s2 = 0.f;
    #pragma unroll
    for (int kk = 0; kk < 8; kk++) { s1 += sm->a.red[kk]; s2 += sm->a.red[kk + 8]; }
    float mean = s1 * (1.0f / 256.0f);
    float var  = fmaxf(s2 * (1.0f / 256.0f) - mean * mean, 0.f);
    if (t < 256) {
        float r = (x - mean) * rsqrtf(var + 1e-5f) * lng[t] + lnb[t];
        g_q[m * 256 + t] = r;
        if (qsave) qsave[t] = r;
    }
    __syncthreads();
}

// ---------------- full attention for query m ----------------
__device__ void attn_full(Smem* sm, int m,
                          const __half* __restrict__ WoT, const float* __restrict__ bo,
                          const float* __restrict__ lng, const float* __restrict__ lnb,
                          float* qsave)
{
    int t = threadIdx.x, lane = t & 31, w = t >> 5;
    int h = w >> 1, part = w & 1;
    int jb = part * 64;

    if (t < 256) sm->a.q[t] = g_qh[m * 256 + t];
    __syncthreads();

    const float* kTh = g_kT + (h * 32) * NQ;
    float s0 = 0.f, s1 = 0.f;
    #pragma unroll
    for (int d = 0; d < 32; d++) {
        float qd = sm->a.q[h * 32 + d];
        s0 = fmaf(qd, kTh[d * NQ + jb + lane], s0);
        s1 = fmaf(qd, kTh[d * NQ + jb + 32 + lane], s1);
    }
    s0 *= 0.17677669529663687f;   // 1/sqrt(32)
    s1 *= 0.17677669529663687f;

    float mx = fmaxf(s0, s1);
    #pragma unroll
    for (int o = 16; o; o >>= 1) mx = fmaxf(mx, __shfl_xor_sync(0xffffffffu, mx, o));
    if (lane == 0) sm->a.mxp[w] = mx;
    __syncthreads();
    mx = fmaxf(sm->a.mxp[h * 2], sm->a.mxp[h * 2 + 1]);

    float e0 = __expf(s0 - mx), e1 = __expf(s1 - mx);
    float ps = warp_red(e0 + e1);
    if (lane == 0) sm->a.sump[w] = ps;
    __syncthreads();
    float inv = 1.0f / (sm->a.sump[h * 2] + sm->a.sump[h * 2 + 1]);

    sm->a.Ps[h * 128 + jb + lane]      = e0 * inv;
    sm->a.Ps[h * 128 + jb + 32 + lane] = e1 * inv;
    __syncthreads();

    float ov = 0.f;
    #pragma unroll 4
    for (int j = jb; j < jb + 64; j++)
        ov = fmaf(sm->a.Ps[h * 128 + j], g_vh[j * 256 + h * 32 + lane], ov);
    if (part == 1) sm->a.ovp[h * 32 + lane] = ov;
    __syncthreads();
    if (part == 0) sm->a.ao[h * 32 + lane] = ov + sm->a.ovp[h * 32 + lane];
    __syncthreads();

    mvT_256to256_h(sm->a.ao, WoT, bo, sm->a.tmpv, sm->a.pbuf);

    resln_inblock(sm, m, lng, lnb, qsave);
}

// ---------------- traj head stage 2 ----------------
__device__ void traj2_stage(Smem* sm, int m, const float* __restrict__ w2,
                            const float* __restrict__ b2, float* __restrict__ outp)
{
    int t = threadIdx.x, lane = t & 31, w = t >> 5;
    const float* hr = g_h + m * 512;
    if (w < 11) {
        const float4* h4 = (const float4*)hr;
        const float4* w4 = (const float4*)(w2 + w * 512);
        float s = dot4(h4[lane], w4[lane]) + dot4(h4[lane + 32], w4[lane + 32]) +
                  dot4(h4[lane + 64], w4[lane + 64]) + dot4(h4[lane + 96], w4[lane + 96]);
        s = warp_red(s);
        if (lane == 0) {
            float v = s + b2[w];
            sm->s.tp[w]      = v;
            outp[m * 11 + w] = v;
        }
    }
    __syncthreads();
}

// accumulate 16 fp8 channels (uint4) * dup'd half2 weight into 8 half2 accumulators
#define ACC16(va, q, wh) do {                                                   \
    va[0] = __hfma2(cvt8((unsigned short)(q).x),         (wh), va[0]);          \
    va[1] = __hfma2(cvt8((unsigned short)((q).x >> 16)), (wh), va[1]);          \
    va[2] = __hfma2(cvt8((unsigned short)(q).y),         (wh), va[2]);          \
    va[3] = __hfma2(cvt8((unsigned short)((q).y >> 16)), (wh), va[3]);          \
    va[4] = __hfma2(cvt8((unsigned short)(q).z),         (wh), va[4]);          \
    va[5] = __hfma2(cvt8((unsigned short)((q).z >> 16)), (wh), va[5]);          \
    va[6] = __hfma2(cvt8((unsigned short)(q).w),         (wh), va[6]);          \
    va[7] = __hfma2(cvt8((unsigned short)((q).w >> 16)), (wh), va[7]);          \
} while (0)

// ---------------- sampling for query m -> sm->s.agg (fp8 features) ----------------
__device__ void sample_stage(Smem* sm, int m, const float* __restrict__ calib,
                             const float* __restrict__ ego)
{
    int t = threadIdx.x;

    if (t < 12) {
        int ci = t % CAMSN, tt = t / CAMSN;
        float* d = sm->s.ctc[t];
        d[0] = ego[tt * 4 + 3] - ego[1 * 4 + 3];
        d[1] = ego[tt * 4 + 0];
        d[2] = ego[tt * 4 + 1];
        float eyaw = ego[tt * 4 + 2];
        d[3] = cosf(eyaw);
        d[4] = sinf(eyaw);
        const float* cal = calib + ci * 8;
        d[5]  = cal[0]; d[6]  = cal[1]; d[7]  = cal[2]; d[8] = cal[3];
        d[9]  = cal[4]; d[10] = cal[5]; d[11] = cal[6];
        d[12] = cosf(cal[7]);
        d[13] = sinf(cal[7]);
    } else if (t == 12) {
        float yaw = sm->s.tp[7];
        sm->s.cs[0] = cosf(yaw);
        sm->s.cs[1] = sinf(yaw);
    }
    __syncthreads();

    // Phase A: project 1800 taps (invalid -> row 0, weight 0); weights as dup'd half2
    for (int idx = t; idx < NTAPS; idx += NT) {
        int pt  = idx % NPTS;
        int ctc = idx / NPTS;
        int ci  = ctc % CAMSN;
        int tt  = ctc / CAMSN;
        const float* d = sm->s.ctc[tt * CAMSN + ci];
        float dt = d[0], ex = d[1], ey = d[2], ce = d[3], se = d[4];
        float fx = d[5], fy = d[6], cx0 = d[7], cy0 = d[8];
        float txc = d[9], tyc = d[10], tzc = d[11], cc = d[12], sc = d[13];

        int face = pt / 25, sub = pt % 25, dim = face >> 1;
        float sign = (face & 1) ? 1.0f : -1.0f;
        float a = -1.0f + 0.5f * (float)(sub / 5);
        float b = -1.0f + 0.5f * (float)(sub % 5);
        float ux, uy, uz;
        if (dim == 0)      { ux = sign; uy = a;    uz = b; }
        else if (dim == 1) { ux = a;    uy = sign; uz = b; }
        else               { ux = a;    uy = b;    uz = sign; }

        float lx = ux * sm->s.tp[8], ly = uy * sm->s.tp[9], lz = uz * sm->s.tp[10];
        float cyw = sm->s.cs[0], syw = sm->s.cs[1];
        float rx = lx * cyw - ly * syw;
        float ry = lx * syw + ly * cyw;
        float cx = sm->s.tp[0] + sm->s.tp[3] * dt + 0.5f * sm->s.tp[5] * dt * dt;
        float cy = sm->s.tp[1] + sm->s.tp[4] * dt + 0.5f * sm->s.tp[6] * dt * dt;
        float wx = rx + cx, wy = ry + cy, wz = lz + sm->s.tp[2];
        float pxr = wx - ex, pyr = wy - ey;
        float gx =  pxr * ce + pyr * se;
        float gy = -pxr * se + pyr * ce;

        float px = gx - txc, py = gy - tyc, pz = wz - tzc;
        float fwd  =  px * cc + py * sc;
        float left = -px * sc + py * cc;
        float zc = fwd, xc = -left, yc = -pz;
        float zs = fmaxf(zc, 0.1f);
        float u = fx * xc / zs + cx0;
        float v = fy * yc / zs + cy0;
        bool valid = (zc > 0.1f) && (u >= 0.f) && (u < 1.f) && (v >= 0.f) && (v < 1.f);

        uint4 wq = make_uint4(0u, 0u, 0u, 0u);
        int rowv = 0;
        if (valid) {
            float pxi = u * 159.0f;
            float pyi = v * 63.0f;
            float x0f = floorf(pxi), y0f = floorf(pyi);
            int x0 = (int)x0f, y0 = (int)y0f;
            float wxk = pxi - x0f, wyk = pyi - y0f;
            rowv = (ci * TSTEP + tt) * PLANE + y0 * WID + x0;
            __half2 h00 = __float2half2_rn((1.f - wxk) * (1.f - wyk));
            __half2 h01 = __float2half2_rn(wxk * (1.f - wyk));
            __half2 h10 = __float2half2_rn((1.f - wxk) * wyk);
            __half2 h11 = __float2half2_rn(wxk * wyk);
            wq.x = *(unsigned*)&h00;
            wq.y = *(unsigned*)&h01;
            wq.z = *(unsigned*)&h10;
            wq.w = *(unsigned*)&h11;
        }
        sm->s.row[idx] = rowv;
        sm->s.w[idx]   = wq;
    }
    __syncthreads();

    // Phase B: 32 half-warp groups; lane = 16 channels via uint4 (LDG.128, fp8),
    // half2 accumulation flushed to fp32 every 8 taps.
    int g = t >> 4;            // 0..31
    int l = t & 15;            // 16 channels: 16l .. 16l+15
    __half2 vacc[8];
    float   facc[16];
    #pragma unroll
    for (int j = 0; j < 8; j++)  vacc[j] = __float2half2_rn(0.f);
    #pragma unroll
    for (int j = 0; j < 16; j++) facc[j] = 0.f;

    const uint4* fb = (const uint4*)g_feat8;   // row stride = 256B/16 = 16 uint4
    int it = 0;
    #pragma unroll 2
    for (int i = g; i < NTAPS; i += 32, it++) {
        int row = sm->s.row[i];
        uint4 wq = sm->s.w[i];
        __half2 w00 = *(__half2*)&wq.x;
        __half2 w01 = *(__half2*)&wq.y;
        __half2 w10 = *(__half2*)&wq.z;
        __half2 w11 = *(__half2*)&wq.w;
        const uint4* p = fb + (size_t)row * 16 + l;
        uint4 q00 = p[0];
        uint4 q01 = p[16];
        uint4 q10 = p[WID * 16];
        uint4 q11 = p[WID * 16 + 16];
        ACC16(vacc, q00, w00);
        ACC16(vacc, q01, w01);
        ACC16(vacc, q10, w10);
        ACC16(vacc, q11, w11);
        if ((it & 7) == 7) {
            #pragma unroll
            for (int j = 0; j < 8; j++) {
                float2 f = __half22float2(vacc[j]);
                facc[2*j]   += f.x;
                facc[2*j+1] += f.y;
                vacc[j] = __float2half2_rn(0.f);
            }
        }
    }
    #pragma unroll
    for (int j = 0; j < 8; j++) {
        float2 f = __half22float2(vacc[j]);
        facc[2*j]   += f.x;
        facc[2*j+1] += f.y;
    }
    __syncthreads();   // all reads of w/row complete; safe to reuse as reduce buffer

    // deterministic tree reduce 32 -> 1 over the dead w/row smem region
    {
        float4* rbuf = (float4*)sm->s.w;
        const int offs[5] = {0, 1024, 1536, 1792, 1920};
        const int stp[5]  = {16, 8, 4, 2, 1};
        #pragma unroll
        for (int s = 0; s < 5; s++) {
            int st = stp[s];
            if (g >= st && g < 2 * st) {
                float4* dp = rbuf + offs[s] + (g - st) * 64 + l * 4;
                dp[0] = make_float4(facc[0],  facc[1],  facc[2],  facc[3]);
                dp[1] = make_float4(facc[4],  facc[5],  facc[6],  facc[7]);
                dp[2] = make_float4(facc[8],  facc[9],  facc[10], facc[11]);
                dp[3] = make_float4(facc[12], facc[13], facc[14], facc[15]);
            }
            __syncthreads();
            if (g < st) {
                const float4* sp = rbuf + offs[s] + g * 64 + l * 4;
                float4 b0 = sp[0], b1 = sp[1], b2 = sp[2], b3 = sp[3];
                facc[0]+=b0.x;  facc[1]+=b0.y;  facc[2]+=b0.z;  facc[3]+=b0.w;
                facc[4]+=b1.x;  facc[5]+=b1.y;  facc[6]+=b1.z;  facc[7]+=b1.w;
                facc[8]+=b2.x;  facc[9]+=b2.y;  facc[10]+=b2.z; facc[11]+=b2.w;
                facc[12]+=b3.x; facc[13]+=b3.y; facc[14]+=b3.z; facc[15]+=b3.w;
            }
        }
    }
    if (g == 0) {
        const float sc = 1.0f / 1800.0f;
        *(float4*)&sm->s.agg[l*16 + 0]  = make_float4(facc[0]*sc,  facc[1]*sc,  facc[2]*sc,  facc[3]*sc);
        *(float4*)&sm->s.agg[l*16 + 4]  = make_float4(facc[4]*sc,  facc[5]*sc,  facc[6]*sc,  facc[7]*sc);
        *(float4*)&sm->s.agg[l*16 + 8]  = make_float4(facc[8]*sc,  facc[9]*sc,  facc[10]*sc, facc[11]*sc);
        *(float4*)&sm->s.agg[l*16 + 12] = make_float4(facc[12]*sc, facc[13]*sc, facc[14]*sc, facc[15]*sc);
    }
    __syncthreads();
}

// ---------------- persistent mega-kernel ----------------
__global__ void __launch_bounds__(NT, 1)
decoder_kernel(const float* __restrict__ features, const float* __restrict__ calib,
               const float* __restrict__ ego, const float* __restrict__ queries,
               const float* __restrict__ tw1, const float* __restrict__ tb1,
               const float* __restrict__ tw2, const float* __restrict__ tb2,
               const float* __restrict__ fmw1, const float* __restrict__ fmb1,
               const float* __restrict__ fmw2, const float* __restrict__ fmb2,
               const float* __restrict__ saiw, const float* __restrict__ saib,
               const float* __restrict__ saow, const float* __restrict__ saob,
               const float* __restrict__ caiw, const float* __restrict__ caib,
               const float* __restrict__ caow, const float* __restrict__ caob,
               const float* __restrict__ l1w,  const float* __restrict__ l1b,
               const float* __restrict__ l2w,  const float* __restrict__ l2b,
               const float* __restrict__ n1g,  const float* __restrict__ n1b,
               const float* __restrict__ n2g,  const float* __restrict__ n2b,
               const float* __restrict__ n3g,  const float* __restrict__ n3b,
               float* __restrict__ out)
{
    __shared__ Smem sm;
    int m = blockIdx.x;
    int t = threadIdx.x;
    int half = t >> 8;
    int tl   = t & 255;
    int barid = half + 1;
    SmemGemm* sg = &sm.g2.h[half];

    unsigned bar0 = 0;
    if (t == 0)
        asm volatile("ld.acquire.gpu.global.u32 %0, [%1];" : "=r"(bar0) : "l"(&g_bar_gen));
    unsigned barcnt = 0;

    // prologue: copy queries (own row only); transpose features -> fp8; fp16 weight transposes
    if (t < 256) g_q[m * 256 + t] = queries[m * 256 + t];
    {
        const int PT = PLANE / 32;                   // 320
        const int CT = CFCH / 32;                    // 8
        const int NTILE = CAMSN * TSTEP * PT * CT;   // 30720
        int tx = t & 31, ty = t >> 5;
        int pc = t & 15, pp = t >> 4;
        for (int tile = blockIdx.x; tile < NTILE; tile += NB) {
            int ct  = tile / (PT * CT);
            int rem = tile % (PT * CT);
            int p0 = (rem % PT) * 32;
            int c0 = (rem / PT) * 32;
            const float* in = features + (size_t)ct * CFCH * PLANE;
            unsigned char* op = g_feat8 + (size_t)ct * CFCH * PLANE;
            #pragma unroll
            for (int i = 0; i < 32; i += 16)
                sm.t.tile[ty + i][tx] = in[(size_t)(c0 + ty + i) * PLANE + p0 + tx];
            __syncthreads();
            {
                float lo = sm.t.tile[2 * pc + 0][pp];
                float hi = sm.t.tile[2 * pc + 1][pp];
                unsigned short v = pack8(hi, lo);
                *(unsigned short*)(op + (size_t)(p0 + pp) * CFCH + c0 + 2 * pc) = v;
            }
            __syncthreads();
        }
    }
    wtransH(&sm, fmw1, g_fmw1T, 512, 256);
    wtransH(&sm, fmw2, g_fmw2T, 256, 512);
    for (int li = 0; li < 6; li++) {
        wtransH(&sm, saow + li * 65536,  g_saowT + li * 65536,  256, 256);
        wtransH(&sm, caow + li * 65536,  g_caowT + li * 65536,  256, 256);
        wtransH(&sm, l1w  + li * 131072, g_l1wT  + li * 131072, 512, 256);
        wtransH(&sm, l2w  + li * 131072, g_l2wT  + li * 131072, 256, 512);
    }
    // No grid sync here: layer-0 S1 reads `queries` + input weights only;
    // the post-S1 grid sync orders all prologue writes before S2.

    for (int li = 0; li < 6; li++) {
        const float* saiw_l = saiw + li * 768 * 256;
        const float* saib_l = saib + li * 768;
        const float* caiw_l = caiw + li * 768 * 256;
        const float* caib_l = caib + li * 768;
        const float* qsrc = (li == 0) ? queries : g_q;

        // ---- S1: GEMM: traj1 (64 tiles) + SA QKV (96 tiles), both read pre-SA q
        for (int tile = blockIdx.x * 2 + half; tile < 160; tile += 256) {
            if (tile < 64)
                gemm_tile<1,0>(sg, tl, barid, qsrc, tw1, tb1, g_h, 256, 512,
                               (tile & 7) * 16, (tile >> 3) * 64);
            else {
                int u = tile - 64;
                gemm_tile<0,1>(sg, tl, barid, qsrc, saiw_l, saib_l, nullptr, 256, 768,
                               (u & 7) * 16, (u >> 3) * 64);
            }
        }
        grid_sync(bar0, barcnt);

        // ---- S2 per-query: SA attn + traj2 + sampling + feature MLP -> g_mem[m]
        attn_full(&sm, m, g_saowT + li * 65536, saob + li * 256,
                  n1g + li * 256, n1b + li * 256, nullptr);
        traj2_stage(&sm, m, tw2, tb2, out + li * 1408);
        sample_stage(&sm, m, calib, ego);
        mvT_256to512_h(sm.s.agg, g_fmw1T, fmb1, sm.s.h, sm.a.pbuf);
        mvT_512to256_h(sm.s.h, g_fmw2T, fmb2, g_mem + m * 256, sm.a.pbuf);
        grid_sync(bar0, barcnt);

        // ---- S3: GEMM: CA q-proj (32 tiles, g_q) + CA kv-proj (64 tiles, g_mem)
        for (int tile = blockIdx.x * 2 + half; tile < 96; tile += 256) {
            if (tile < 32)
                gemm_tile<0,1>(sg, tl, barid, g_q, caiw_l, caib_l, nullptr, 256, 768,
                               (tile & 7) * 16, (tile >> 3) * 64);
            else {
                int u = tile - 32;
                gemm_tile<0,1>(sg, tl, barid, g_mem, caiw_l, caib_l, nullptr, 256, 768,
                               (u & 7) * 16, 256 + (u >> 3) * 64);
            }
        }
        grid_sync(bar0, barcnt);

        // ---- S4 per-query: CA attn (+resln2, save qrow) + FFN + resln3
        attn_full(&sm, m, g_caowT + li * 65536, caob + li * 256,
                  n2g + li * 256, n2b + li * 256, sm.s.agg);
        mvT_256to512_h(sm.s.agg, g_l1wT + li * 131072, l1b + li * 512, sm.s.h, sm.a.pbuf);
        mvT_512to256_h(sm.s.h, g_l2wT + li * 131072, l2b + li * 256, sm.a.tmpv, sm.a.pbuf);
        resln_inblock(&sm, m, n3g + li * 256, n3b + li * 256, nullptr);
        grid_sync(bar0, barcnt);
    }

    // epilogue: final traj head
    for (int tile = blockIdx.x * 2 + half; tile < 64; tile += 256)
        gemm_tile<1,0>(sg, tl, barid, g_q, tw1, tb1, g_h, 256, 512,
                       (tile & 7) * 16, (tile >> 3) * 64);
    grid_sync(bar0, barcnt);
    traj2_stage(&sm, m, tw2, tb2, out + 6 * 1408);
}

// ---------------- host: one launch ----------------
extern "C" void kernel_launch(void* const* d_in, const int* in_sizes, int n_in,
                              void* d_out, int out_size)
{
    const float* features = (const float*)d_in[0];
    const float* calib    = (const float*)d_in[1];
    const float* ego      = (const float*)d_in[2];
    const float* queries  = (const float*)d_in[3];
    const float* tw1  = (const float*)d_in[5];
    const float* tb1  = (const float*)d_in[6];
    const float* tw2  = (const float*)d_in[7];
    const float* tb2  = (const float*)d_in[8];
    const float* fmw1 = (const float*)d_in[9];
    const float* fmb1 = (const float*)d_in[10];
    const float* fmw2 = (const float*)d_in[11];
    const float* fmb2 = (const float*)d_in[12];
    const float* saiw = (const float*)d_in[13];
    const float* saib = (const float*)d_in[14];
    const float* saow = (const float*)d_in[15];
    const float* saob = (const float*)d_in[16];
    const float* caiw = (const float*)d_in[17];
    const float* caib = (const float*)d_in[18];
    const float* caow = (const float*)d_in[19];
    const float* caob = (const float*)d_in[20];
    const float* l1w  = (const float*)d_in[21];
    const float* l1b  = (const float*)d_in[22];
    const float* l2w  = (const float*)d_in[23];
    const float* l2b  = (const float*)d_in[24];
    const float* n1g  = (const float*)d_in[25];
    const float* n1b  = (const float*)d_in[26];
    const float* n2g  = (const float*)d_in[27];
    const float* n2b  = (const float*)d_in[28];
    const float* n3g  = (const float*)d_in[29];
    const float* n3b  = (const float*)d_in[30];
    float* out = (float*)d_out;

    decoder_kernel<<<NB, NT>>>(features, calib, ego, queries,
                               tw1, tb1, tw2, tb2,
                               fmw1, fmb1, fmw2, fmb2,
                               saiw, saib, saow, saob,
                               caiw, caib, caow, caob,
                               l1w, l1b, l2w, l2b,
                               n1g, n1b, n2g, n2b, n3g, n3b,
                               out);
}

// round 17
// speedup vs baseline: 1.1410x; 1.1410x over previous
#include <cuda_runtime.h>
#include <cuda_fp16.h>
#include <math.h>

#define NQ    128
#define ED    256
#define DFFD  512
#define CAMSN 6
#define TSTEP 2
#define CFCH  256
#define HGT   64
#define WID   160
#define PLANE (HGT*WID)           /* 10240 */
#define NPTS  150
#define NTAPS (NPTS*CAMSN*TSTEP)  /* 1800 */
#define NB    128
#define NT    512

// ---------------- device scratch ----------------
__device__ float  g_q    [NQ*ED];
__device__ float  g_h    [NQ*DFFD];
__device__ float  g_qh   [NQ*ED];
__device__ float  g_kT   [ED*NQ];     // SA K transposed: [256 dims][128 queries]
__device__ float  g_vh   [NQ*ED];     // SA V rows
__device__ float  g_kT2  [ED*NQ];     // CA K transposed
__device__ float  g_vh2  [NQ*ED];     // CA V rows
__device__ __align__(16) unsigned char g_feat8[(size_t)CAMSN*TSTEP*PLANE*CFCH]; // 31.5 MB fp8 pixel-major

// transposed matvec weights, fp16: WT[k][c]
__device__ __align__(16) __half g_fmw1T[256*512];
__device__ __align__(16) __half g_fmw2T[512*256];
__device__ __align__(16) __half g_l1wT [6*256*512];
__device__ __align__(16) __half g_l2wT [6*512*256];
__device__ __align__(16) __half g_saowT[6*256*256];
__device__ __align__(16) __half g_caowT[6*256*256];
// transposed CA in-projection weights, fp32 (precision held constant for bisection)
__device__ __align__(16) float  g_caiwTf[6*256*768];

__device__ unsigned g_bar_arrive;
__device__ unsigned g_bar_gen;

// ---------------- shared memory union ----------------
struct SmemGemm   { float As[2][32][20]; float Ws[2][32][68]; };   // 22528 B
struct SmemGemm2  { SmemGemm h[2]; };                              // 45056 B
struct SmemS2 {                       // per-query stage scratch
    uint4  w[NTAPS];                  // 28800 B (sampling weights; reused as reduce buf)
    int    row[NTAPS];                // 7200 B
    float  agg[256];
    float  h[512];
    float  tp[11];
    float  cs[2];
    float  ctc[12][14];
};
struct SmemAttn {
    float  q[256];
    float  Ps[8*128];
    float  mxp[16];
    float  sump[16];
    float  ovp[256];
    float  ao[256];
    float  tmpv[256];
    float  red[16];
    float4 pbuf[960];                 // matvec partials
};
struct SmemTrans  { float tile[32][33]; };
union __align__(16) Smem {
    SmemGemm2  g2;
    SmemS2     s;
    SmemAttn   a;
    SmemTrans  t;
};

// ---------------- fp8 converts ----------------
__device__ __forceinline__ __half2 cvt8(unsigned short v)
{
    unsigned r;
    asm("cvt.rn.f16x2.e4m3x2 %0, %1;" : "=r"(r) : "h"(v));
    return *(__half2*)&r;
}
__device__ __forceinline__ unsigned short pack8(float hi, float lo)
{
    unsigned short r;
    asm("cvt.rn.satfinite.e4m3x2.f32 %0, %1, %2;" : "=h"(r) : "f"(hi), "f"(lo));
    return r;
}

// ---------------- named barrier for 256-thread half-CTA ----------------
__device__ __forceinline__ void half_bar(int id)
{
    asm volatile("bar.sync %0, 256;" :: "r"(id) : "memory");
}

// ---------------- software grid barrier: release/acquire, replay-safe ----------------
__device__ __forceinline__ void grid_sync(unsigned bar0, unsigned& cnt)
{
    __syncthreads();
    cnt++;
    if (threadIdx.x == 0) {
        unsigned target = bar0 + cnt;
        unsigned t;
        asm volatile("atom.release.gpu.global.add.u32 %0, [%1], 1;"
                     : "=r"(t) : "l"(&g_bar_arrive) : "memory");
        if (t == (unsigned)(NB - 1)) {
            g_bar_arrive = 0u;
            asm volatile("st.release.gpu.global.u32 [%0], %1;"
                         :: "l"(&g_bar_gen), "r"(target) : "memory");
        } else {
            unsigned cur;
            do {
                asm volatile("ld.acquire.gpu.global.u32 %0, [%1];"
                             : "=r"(cur) : "l"(&g_bar_gen) : "memory");
            } while ((int)(cur - target) < 0);
        }
    }
    __syncthreads();
}

__device__ __forceinline__ float warp_red(float v)
{
    #pragma unroll
    for (int o = 16; o; o >>= 1) v += __shfl_xor_sync(0xffffffffu, v, o);
    return v;
}

__device__ __forceinline__ float dot4(float4 a, float4 b)
{
    return fmaf(a.x, b.x, fmaf(a.y, b.y, fmaf(a.z, b.z, a.w * b.w)));
}

// ---------------- fp32->fp16 transposed weight staging ----------------
__device__ void wtransH(Smem* sm, const float* __restrict__ src, __half* __restrict__ dst,
                        int R, int C)
{
    int t = threadIdx.x;
    int tx = t & 31, ty = t >> 5;     // 32 x 16
    int rt = R >> 5;
    int nt = rt * (C >> 5);
    for (int tile = blockIdx.x; tile < nt; tile += NB) {
        int r0 = (tile % rt) << 5;
        int c0 = (tile / rt) << 5;
        #pragma unroll
        for (int i = 0; i < 32; i += 16)
            sm->t.tile[ty + i][tx] = src[(size_t)(r0 + ty + i) * C + c0 + tx];
        __syncthreads();
        #pragma unroll
        for (int i = 0; i < 32; i += 16)
            dst[(size_t)(c0 + ty + i) * R + r0 + tx] = __float2half_rn(sm->t.tile[tx][ty + i]);
        __syncthreads();
    }
}

// ---------------- fp32 transposed weight staging ----------------
__device__ void wtrans32(Smem* sm, const float* __restrict__ src, float* __restrict__ dst,
                         int R, int C)
{
    int t = threadIdx.x;
    int tx = t & 31, ty = t >> 5;
    int rt = R >> 5;
    int nt = rt * (C >> 5);
    for (int tile = blockIdx.x; tile < nt; tile += NB) {
        int r0 = (tile % rt) << 5;
        int c0 = (tile / rt) << 5;
        #pragma unroll
        for (int i = 0; i < 32; i += 16)
            sm->t.tile[ty + i][tx] = src[(size_t)(r0 + ty + i) * C + c0 + tx];
        __syncthreads();
        #pragma unroll
        for (int i = 0; i < 32; i += 16)
            dst[(size_t)(c0 + ty + i) * R + r0 + tx] = sm->t.tile[tx][ty + i];
        __syncthreads();
    }
}

// ---------------- one 16x64 GEMM tile on a 256-thread half, dbuf K=32 ----------------
template <int ACT, int QKV>
__device__ void gemm_tile(SmemGemm* sg, int tl, int barid,
                          const float* __restrict__ A,
                          const float* __restrict__ W, const float* __restrict__ Bb,
                          float* __restrict__ C, int K, int ldc, int m0, int n0)
{
    int tx = tl & 15;
    int ty = tl >> 4;
    float acc[4] = {0.f, 0.f, 0.f, 0.f};

#define LOAD_CHUNK(k0, b) do {                                                  \
        if (tl < 128) {                                                         \
            int r = tl >> 3, kq = tl & 7;                                       \
            float4 v = *(const float4*)&A[(m0 + r) * K + (k0) + kq * 4];        \
            sg->As[b][kq*4+0][r] = v.x; sg->As[b][kq*4+1][r] = v.y;             \
            sg->As[b][kq*4+2][r] = v.z; sg->As[b][kq*4+3][r] = v.w;             \
        }                                                                        \
        {                                                                        \
            int r = tl >> 2, kq = tl & 3;                                       \
            float4 v0 = *(const float4*)&W[(n0 + r) * K + (k0) + kq * 4];       \
            float4 v1 = *(const float4*)&W[(n0 + r) * K + (k0) + 16 + kq * 4];  \
            sg->Ws[b][kq*4+0][r] = v0.x; sg->Ws[b][kq*4+1][r] = v0.y;           \
            sg->Ws[b][kq*4+2][r] = v0.z; sg->Ws[b][kq*4+3][r] = v0.w;           \
            sg->Ws[b][16+kq*4+0][r] = v1.x; sg->Ws[b][16+kq*4+1][r] = v1.y;     \
            sg->Ws[b][16+kq*4+2][r] = v1.z; sg->Ws[b][16+kq*4+3][r] = v1.w;     \
        }                                                                        \
    } while (0)

    LOAD_CHUNK(0, 0);
    half_bar(barid);
    int p = 0;
    for (int k0 = 0; k0 < K; k0 += 32) {
        if (k0 + 32 < K) LOAD_CHUNK(k0 + 32, p ^ 1);
        #pragma unroll
        for (int k = 0; k < 32; k++) {
            float a  = sg->As[p][k][ty];
            float4 w = *(const float4*)&sg->Ws[p][k][tx*4];
            acc[0] = fmaf(a, w.x, acc[0]);
            acc[1] = fmaf(a, w.y, acc[1]);
            acc[2] = fmaf(a, w.z, acc[2]);
            acc[3] = fmaf(a, w.w, acc[3]);
        }
        half_bar(barid);
        p ^= 1;
    }
#undef LOAD_CHUNK

    int row = m0 + ty;
    int col = n0 + tx * 4;
    float4 bv = *(const float4*)&Bb[col];
    float4 r;
    r.x = acc[0] + bv.x;
    r.y = acc[1] + bv.y;
    r.z = acc[2] + bv.z;
    r.w = acc[3] + bv.w;
    if (ACT) {
        r.x = fmaxf(r.x, 0.f); r.y = fmaxf(r.y, 0.f);
        r.z = fmaxf(r.z, 0.f); r.w = fmaxf(r.w, 0.f);
    }
    if (QKV) {
        if (col < 256) {
            *(float4*)&g_qh[row * 256 + col] = r;
        } else if (col < 512) {
            int kd = col - 256;
            g_kT[(kd+0)*NQ + row] = r.x;
            g_kT[(kd+1)*NQ + row] = r.y;
            g_kT[(kd+2)*NQ + row] = r.z;
            g_kT[(kd+3)*NQ + row] = r.w;
        } else {
            *(float4*)&g_vh[row * 256 + (col - 512)] = r;
        }
    } else {
        *(float4*)&C[row * ldc + col] = r;
    }
}

// ---------------- generic fp32 split-K matvec ----------------
// out[COLS] = act(WT^T x[KIN] + b). wt is column-offset; RSF = weight row stride in float4.
template<int COLS, int KIN, int RSF, int ACT>
__device__ void mvT_f(const float* __restrict__ xs, const float4* __restrict__ wt,
                      const float* __restrict__ Bb, float* __restrict__ outv,
                      float4* pbuf)
{
    constexpr int QD = COLS / 4;      // column quads
    constexpr int KS = NT / QD;       // k-splits
    constexpr int KK = KIN / KS;      // k per split
    int t = threadIdx.x;
    int quad = t & (QD - 1);
    int ks   = t / QD;
    float4 acc = {0.f, 0.f, 0.f, 0.f};
    int kb = ks * KK;
    #pragma unroll 8
    for (int k = 0; k < KK; k++) {
        float xk = xs[kb + k];
        float4 w = wt[(size_t)(kb + k) * RSF + quad];
        acc.x = fmaf(xk, w.x, acc.x);
        acc.y = fmaf(xk, w.y, acc.y);
        acc.z = fmaf(xk, w.z, acc.z);
        acc.w = fmaf(xk, w.w, acc.w);
    }
    if (ks > 0) pbuf[(ks - 1) * QD + quad] = acc;
    __syncthreads();
    if (ks == 0) {
        #pragma unroll
        for (int p = 0; p < KS - 1; p++) {
            float4 b = pbuf[p * QD + quad];
            acc.x += b.x; acc.y += b.y; acc.z += b.z; acc.w += b.w;
        }
        float4 bb = *(const float4*)&Bb[quad * 4];
        acc.x += bb.x; acc.y += bb.y; acc.z += bb.z; acc.w += bb.w;
        if (ACT) {
            acc.x = fmaxf(acc.x, 0.f); acc.y = fmaxf(acc.y, 0.f);
            acc.z = fmaxf(acc.z, 0.f); acc.w = fmaxf(acc.w, 0.f);
        }
        *(float4*)&outv[quad * 4] = acc;
    }
    __syncthreads();
}

// ---------------- fp16-weight split-K matvecs: WT half[k][c] ----------------
__device__ void mvT_256to512_h(const float* __restrict__ xs, const __half* __restrict__ WT,
                               const float* __restrict__ Bb, float* __restrict__ hs,
                               float4* pbuf)
{
    int t = threadIdx.x;
    int oct = t & 63;
    int ks  = t >> 6;               // 0..7
    const uint4* wt = (const uint4*)WT;   // row stride 64 uint4
    float4 a0 = {0.f,0.f,0.f,0.f}, a1 = {0.f,0.f,0.f,0.f};
    int kb = ks * 32;
    #pragma unroll 8
    for (int k = 0; k < 32; k++) {
        float xk = xs[kb + k];
        uint4 w = wt[(size_t)(kb + k) * 64 + oct];
        float2 f0 = __half22float2(*(const __half2*)&w.x);
        float2 f1 = __half22float2(*(const __half2*)&w.y);
        float2 f2 = __half22float2(*(const __half2*)&w.z);
        float2 f3 = __half22float2(*(const __half2*)&w.w);
        a0.x = fmaf(xk, f0.x, a0.x); a0.y = fmaf(xk, f0.y, a0.y);
        a0.z = fmaf(xk, f1.x, a0.z); a0.w = fmaf(xk, f1.y, a0.w);
        a1.x = fmaf(xk, f2.x, a1.x); a1.y = fmaf(xk, f2.y, a1.y);
        a1.z = fmaf(xk, f3.x, a1.z); a1.w = fmaf(xk, f3.y, a1.w);
    }
    if (ks > 0) {
        pbuf[(ks - 1) * 128 + oct * 2 + 0] = a0;
        pbuf[(ks - 1) * 128 + oct * 2 + 1] = a1;
    }
    __syncthreads();
    if (ks == 0) {
        #pragma unroll
        for (int p = 0; p < 7; p++) {
            float4 b0 = pbuf[p * 128 + oct * 2 + 0];
            float4 b1 = pbuf[p * 128 + oct * 2 + 1];
            a0.x += b0.x; a0.y += b0.y; a0.z += b0.z; a0.w += b0.w;
            a1.x += b1.x; a1.y += b1.y; a1.z += b1.z; a1.w += b1.w;
        }
        float4 bb0 = *(const float4*)&Bb[oct * 8];
        float4 bb1 = *(const float4*)&Bb[oct * 8 + 4];
        a0.x = fmaxf(a0.x + bb0.x, 0.f); a0.y = fmaxf(a0.y + bb0.y, 0.f);
        a0.z = fmaxf(a0.z + bb0.z, 0.f); a0.w = fmaxf(a0.w + bb0.w, 0.f);
        a1.x = fmaxf(a1.x + bb1.x, 0.f); a1.y = fmaxf(a1.y + bb1.y, 0.f);
        a1.z = fmaxf(a1.z + bb1.z, 0.f); a1.w = fmaxf(a1.w + bb1.w, 0.f);
        *(float4*)&hs[oct * 8]     = a0;
        *(float4*)&hs[oct * 8 + 4] = a1;
    }
    __syncthreads();
}

__device__ void mvT_512to256_h(const float* __restrict__ xs, const __half* __restrict__ WT,
                               const float* __restrict__ Bb, float* __restrict__ outv,
                               float4* pbuf)
{
    int t = threadIdx.x;
    int oct = t & 31;
    int ks  = t >> 5;               // 0..15
    const uint4* wt = (const uint4*)WT;   // row stride 32 uint4
    float4 a0 = {0.f,0.f,0.f,0.f}, a1 = {0.f,0.f,0.f,0.f};
    int kb = ks * 32;
    #pragma unroll 8
    for (int k = 0; k < 32; k++) {
        float xk = xs[kb + k];
        uint4 w = wt[(size_t)(kb + k) * 32 + oct];
        float2 f0 = __half22float2(*(const __half2*)&w.x);
        float2 f1 = __half22float2(*(const __half2*)&w.y);
        float2 f2 = __half22float2(*(const __half2*)&w.z);
        float2 f3 = __half22float2(*(const __half2*)&w.w);
        a0.x = fmaf(xk, f0.x, a0.x); a0.y = fmaf(xk, f0.y, a0.y);
        a0.z = fmaf(xk, f1.x, a0.z); a0.w = fmaf(xk, f1.y, a0.w);
        a1.x = fmaf(xk, f2.x, a1.x); a1.y = fmaf(xk, f2.y, a1.y);
        a1.z = fmaf(xk, f3.x, a1.z); a1.w = fmaf(xk, f3.y, a1.w);
    }
    if (ks > 0) {
        pbuf[(ks - 1) * 64 + oct * 2 + 0] = a0;
        pbuf[(ks - 1) * 64 + oct * 2 + 1] = a1;
    }
    __syncthreads();
    if (ks == 0) {
        #pragma unroll
        for (int p = 0; p < 15; p++) {
            float4 b0 = pbuf[p * 64 + oct * 2 + 0];
            float4 b1 = pbuf[p * 64 + oct * 2 + 1];
            a0.x += b0.x; a0.y += b0.y; a0.z += b0.z; a0.w += b0.w;
            a1.x += b1.x; a1.y += b1.y; a1.z += b1.z; a1.w += b1.w;
        }
        float4 bb0 = *(const float4*)&Bb[oct * 8];
        float4 bb1 = *(const float4*)&Bb[oct * 8 + 4];
        a0.x += bb0.x; a0.y += bb0.y; a0.z += bb0.z; a0.w += bb0.w;
        a1.x += bb1.x; a1.y += bb1.y; a1.z += bb1.z; a1.w += bb1.w;
        *(float4*)&outv[oct * 8]     = a0;
        *(float4*)&outv[oct * 8 + 4] = a1;
    }
    __syncthreads();
}

__device__ void mvT_256to256_h(const float* __restrict__ xs, const __half* __restrict__ WT,
                               const float* __restrict__ Bb, float* __restrict__ outv,
                               float4* pbuf)
{
    int t = threadIdx.x;
    int oct = t & 31;
    int ks  = t >> 5;               // 0..15
    const uint4* wt = (const uint4*)WT;   // row stride 32 uint4
    float4 a0 = {0.f,0.f,0.f,0.f}, a1 = {0.f,0.f,0.f,0.f};
    int kb = ks * 16;
    #pragma unroll 8
    for (int k = 0; k < 16; k++) {
        float xk = xs[kb + k];
        uint4 w = wt[(size_t)(kb + k) * 32 + oct];
        float2 f0 = __half22float2(*(const __half2*)&w.x);
        float2 f1 = __half22float2(*(const __half2*)&w.y);
        float2 f2 = __half22float2(*(const __half2*)&w.z);
        float2 f3 = __half22float2(*(const __half2*)&w.w);
        a0.x = fmaf(xk, f0.x, a0.x); a0.y = fmaf(xk, f0.y, a0.y);
        a0.z = fmaf(xk, f1.x, a0.z); a0.w = fmaf(xk, f1.y, a0.w);
        a1.x = fmaf(xk, f2.x, a1.x); a1.y = fmaf(xk, f2.y, a1.y);
        a1.z = fmaf(xk, f3.x, a1.z); a1.w = fmaf(xk, f3.y, a1.w);
    }
    if (ks > 0) {
        pbuf[(ks - 1) * 64 + oct * 2 + 0] = a0;
        pbuf[(ks - 1) * 64 + oct * 2 + 1] = a1;
    }
    __syncthreads();
    if (ks == 0) {
        #pragma unroll
        for (int p = 0; p < 15; p++) {
            float4 b0 = pbuf[p * 64 + oct * 2 + 0];
            float4 b1 = pbuf[p * 64 + oct * 2 + 1];
            a0.x += b0.x; a0.y += b0.y; a0.z += b0.z; a0.w += b0.w;
            a1.x += b1.x; a1.y += b1.y; a1.z += b1.z; a1.w += b1.w;
        }
        float4 bb0 = *(const float4*)&Bb[oct * 8];
        float4 bb1 = *(const float4*)&Bb[oct * 8 + 4];
        a0.x += bb0.x; a0.y += bb0.y; a0.z += bb0.z; a0.w += bb0.w;
        a1.x += bb1.x; a1.y += bb1.y; a1.z += bb1.z; a1.w += bb1.w;
        *(float4*)&outv[oct * 8]     = a0;
        *(float4*)&outv[oct * 8 + 4] = a1;
    }
    __syncthreads();
}

// ---------------- residual add + LayerNorm (single-pass mean/var) ----------------
__device__ void resln_inblock(Smem* sm, int m, const float* __restrict__ lng,
                              const float* __restrict__ lnb, float* qsave)
{
    int t = threadIdx.x, lane = t & 31, w = t >> 5;
    float x = 0.f;
    if (t < 256) x = g_q[m * 256 + t] + sm->a.tmpv[t];

    float v1 = x, v2 = x * x;
    #pragma unroll
    for (int o = 16; o; o >>= 1) {
        v1 += __shfl_xor_sync(0xffffffffu, v1, o);
        v2 += __shfl_xor_sync(0xffffffffu, v2, o);
    }
    if (lane == 0) { sm->a.red[w] = v1; sm->a.red[w + 8] = v2; }
    __syncthreads();
    float s1 = 0.f, s2 = 0.f;
    #pragma unroll
    for (int kk = 0; kk < 8; kk++) { s1 += sm->a.red[kk]; s2 += sm->a.red[kk + 8]; }
    float mean = s1 * (1.0f / 256.0f);
    float var  = fmaxf(s2 * (1.0f / 256.0f) - mean * mean, 0.f);
    if (t < 256) {
        float r = (x - mean) * rsqrtf(var + 1e-5f) * lng[t] + lnb[t];
        g_q[m * 256 + t] = r;
        if (qsave) qsave[t] = r;
    }
    __syncthreads();
}

// ---------------- attention core for query m; qvec supplied in smem ----------------
__device__ void attn_full(Smem* sm, int m, const float* __restrict__ qvec,
                          const float* __restrict__ kT, const float* __restrict__ vh,
                          const __half* __restrict__ WoT, const float* __restrict__ bo,
                          const float* __restrict__ lng, const float* __restrict__ lnb,
                          float* qsave)
{
    int t = threadIdx.x, lane = t & 31, w = t >> 5;
    int h = w >> 1, part = w & 1;
    int jb = part * 64;

    const float* kTh = kT + (h * 32) * NQ;
    float s0 = 0.f, s1 = 0.f;
    #pragma unroll
    for (int d = 0; d < 32; d++) {
        float qd = qvec[h * 32 + d];
        s0 = fmaf(qd, kTh[d * NQ + jb + lane], s0);
        s1 = fmaf(qd, kTh[d * NQ + jb + 32 + lane], s1);
    }
    s0 *= 0.17677669529663687f;   // 1/sqrt(32)
    s1 *= 0.17677669529663687f;

    float mx = fmaxf(s0, s1);
    #pragma unroll
    for (int o = 16; o; o >>= 1) mx = fmaxf(mx, __shfl_xor_sync(0xffffffffu, mx, o));
    if (lane == 0) sm->a.mxp[w] = mx;
    __syncthreads();
    mx = fmaxf(sm->a.mxp[h * 2], sm->a.mxp[h * 2 + 1]);

    float e0 = __expf(s0 - mx), e1 = __expf(s1 - mx);
    float ps = warp_red(e0 + e1);
    if (lane == 0) sm->a.sump[w] = ps;
    __syncthreads();
    float inv = 1.0f / (sm->a.sump[h * 2] + sm->a.sump[h * 2 + 1]);

    sm->a.Ps[h * 128 + jb + lane]      = e0 * inv;
    sm->a.Ps[h * 128 + jb + 32 + lane] = e1 * inv;
    __syncthreads();

    float ov = 0.f;
    #pragma unroll 4
    for (int j = jb; j < jb + 64; j++)
        ov = fmaf(sm->a.Ps[h * 128 + j], vh[j * 256 + h * 32 + lane], ov);
    if (part == 1) sm->a.ovp[h * 32 + lane] = ov;
    __syncthreads();
    if (part == 0) sm->a.ao[h * 32 + lane] = ov + sm->a.ovp[h * 32 + lane];
    __syncthreads();

    mvT_256to256_h(sm->a.ao, WoT, bo, sm->a.tmpv, sm->a.pbuf);

    resln_inblock(sm, m, lng, lnb, qsave);
}

// ---------------- traj head stage 2 ----------------
__device__ void traj2_stage(Smem* sm, int m, const float* __restrict__ w2,
                            const float* __restrict__ b2, float* __restrict__ outp)
{
    int t = threadIdx.x, lane = t & 31, w = t >> 5;
    const float* hr = g_h + m * 512;
    if (w < 11) {
        const float4* h4 = (const float4*)hr;
        const float4* w4 = (const float4*)(w2 + w * 512);
        float s = dot4(h4[lane], w4[lane]) + dot4(h4[lane + 32], w4[lane + 32]) +
                  dot4(h4[lane + 64], w4[lane + 64]) + dot4(h4[lane + 96], w4[lane + 96]);
        s = warp_red(s);
        if (lane == 0) {
            float v = s + b2[w];
            sm->s.tp[w]      = v;
            outp[m * 11 + w] = v;
        }
    }
    __syncthreads();
}

// accumulate 16 fp8 channels (uint4) * dup'd half2 weight into 8 half2 accumulators
#define ACC16(va, q, wh) do {                                                   \
    va[0] = __hfma2(cvt8((unsigned short)(q).x),         (wh), va[0]);          \
    va[1] = __hfma2(cvt8((unsigned short)((q).x >> 16)), (wh), va[1]);          \
    va[2] = __hfma2(cvt8((unsigned short)(q).y),         (wh), va[2]);          \
    va[3] = __hfma2(cvt8((unsigned short)((q).y >> 16)), (wh), va[3]);          \
    va[4] = __hfma2(cvt8((unsigned short)(q).z),         (wh), va[4]);          \
    va[5] = __hfma2(cvt8((unsigned short)((q).z >> 16)), (wh), va[5]);          \
    va[6] = __hfma2(cvt8((unsigned short)(q).w),         (wh), va[6]);          \
    va[7] = __hfma2(cvt8((unsigned short)((q).w >> 16)), (wh), va[7]);          \
} while (0)

// ---------------- sampling for query m -> sm->s.agg (fp8 features) ----------------
__device__ void sample_stage(Smem* sm, int m, const float* __restrict__ calib,
                             const float* __restrict__ ego)
{
    int t = threadIdx.x;

    if (t < 12) {
        int ci = t % CAMSN, tt = t / CAMSN;
        float* d = sm->s.ctc[t];
        d[0] = ego[tt * 4 + 3] - ego[1 * 4 + 3];
        d[1] = ego[tt * 4 + 0];
        d[2] = ego[tt * 4 + 1];
        float eyaw = ego[tt * 4 + 2];
        d[3] = cosf(eyaw);
        d[4] = sinf(eyaw);
        const float* cal = calib + ci * 8;
        d[5]  = cal[0]; d[6]  = cal[1]; d[7]  = cal[2]; d[8] = cal[3];
        d[9]  = cal[4]; d[10] = cal[5]; d[11] = cal[6];
        d[12] = cosf(cal[7]);
        d[13] = sinf(cal[7]);
    } else if (t == 12) {
        float yaw = sm->s.tp[7];
        sm->s.cs[0] = cosf(yaw);
        sm->s.cs[1] = sinf(yaw);
    }
    __syncthreads();

    // Phase A: project 1800 taps (invalid -> row 0, weight 0); weights as dup'd half2
    for (int idx = t; idx < NTAPS; idx += NT) {
        int pt  = idx % NPTS;
        int ctc = idx / NPTS;
        int ci  = ctc % CAMSN;
        int tt  = ctc / CAMSN;
        const float* d = sm->s.ctc[tt * CAMSN + ci];
        float dt = d[0], ex = d[1], ey = d[2], ce = d[3], se = d[4];
        float fx = d[5], fy = d[6], cx0 = d[7], cy0 = d[8];
        float txc = d[9], tyc = d[10], tzc = d[11], cc = d[12], sc = d[13];

        int face = pt / 25, sub = pt % 25, dim = face >> 1;
        float sign = (face & 1) ? 1.0f : -1.0f;
        float a = -1.0f + 0.5f * (float)(sub / 5);
        float b = -1.0f + 0.5f * (float)(sub % 5);
        float ux, uy, uz;
        if (dim == 0)      { ux = sign; uy = a;    uz = b; }
        else if (dim == 1) { ux = a;    uy = sign; uz = b; }
        else               { ux = a;    uy = b;    uz = sign; }

        float lx = ux * sm->s.tp[8], ly = uy * sm->s.tp[9], lz = uz * sm->s.tp[10];
        float cyw = sm->s.cs[0], syw = sm->s.cs[1];
        float rx = lx * cyw - ly * syw;
        float ry = lx * syw + ly * cyw;
        float cx = sm->s.tp[0] + sm->s.tp[3] * dt + 0.5f * sm->s.tp[5] * dt * dt;
        float cy = sm->s.tp[1] + sm->s.tp[4] * dt + 0.5f * sm->s.tp[6] * dt * dt;
        float wx = rx + cx, wy = ry + cy, wz = lz + sm->s.tp[2];
        float pxr = wx - ex, pyr = wy - ey;
        float gx =  pxr * ce + pyr * se;
        float gy = -pxr * se + pyr * ce;

        float px = gx - txc, py = gy - tyc, pz = wz - tzc;
        float fwd  =  px * cc + py * sc;
        float left = -px * sc + py * cc;
        float zc = fwd, xc = -left, yc = -pz;
        float zs = fmaxf(zc, 0.1f);
        float u = fx * xc / zs + cx0;
        float v = fy * yc / zs + cy0;
        bool valid = (zc > 0.1f) && (u >= 0.f) && (u < 1.f) && (v >= 0.f) && (v < 1.f);

        uint4 wq = make_uint4(0u, 0u, 0u, 0u);
        int rowv = 0;
        if (valid) {
            float pxi = u * 159.0f;
            float pyi = v * 63.0f;
            float x0f = floorf(pxi), y0f = floorf(pyi);
            int x0 = (int)x0f, y0 = (int)y0f;
            float wxk = pxi - x0f, wyk = pyi - y0f;
            rowv = (ci * TSTEP + tt) * PLANE + y0 * WID + x0;
            __half2 h00 = __float2half2_rn((1.f - wxk) * (1.f - wyk));
            __half2 h01 = __float2half2_rn(wxk * (1.f - wyk));
            __half2 h10 = __float2half2_rn((1.f - wxk) * wyk);
            __half2 h11 = __float2half2_rn(wxk * wyk);
            wq.x = *(unsigned*)&h00;
            wq.y = *(unsigned*)&h01;
            wq.z = *(unsigned*)&h10;
            wq.w = *(unsigned*)&h11;
        }
        sm->s.row[idx] = rowv;
        sm->s.w[idx]   = wq;
    }
    __syncthreads();

    // Phase B: 32 half-warp groups; lane = 16 channels via uint4 (LDG.128, fp8),
    // half2 accumulation flushed to fp32 every 8 taps.
    int g = t >> 4;            // 0..31
    int l = t & 15;            // 16 channels: 16l .. 16l+15
    __half2 vacc[8];
    float   facc[16];
    #pragma unroll
    for (int j = 0; j < 8; j++)  vacc[j] = __float2half2_rn(0.f);
    #pragma unroll
    for (int j = 0; j < 16; j++) facc[j] = 0.f;

    const uint4* fb = (const uint4*)g_feat8;   // row stride = 256B/16 = 16 uint4
    int it = 0;
    #pragma unroll 2
    for (int i = g; i < NTAPS; i += 32, it++) {
        int row = sm->s.row[i];
        uint4 wq = sm->s.w[i];
        __half2 w00 = *(__half2*)&wq.x;
        __half2 w01 = *(__half2*)&wq.y;
        __half2 w10 = *(__half2*)&wq.z;
        __half2 w11 = *(__half2*)&wq.w;
        const uint4* p = fb + (size_t)row * 16 + l;
        uint4 q00 = p[0];
        uint4 q01 = p[16];
        uint4 q10 = p[WID * 16];
        uint4 q11 = p[WID * 16 + 16];
        ACC16(vacc, q00, w00);
        ACC16(vacc, q01, w01);
        ACC16(vacc, q10, w10);
        ACC16(vacc, q11, w11);
        if ((it & 7) == 7) {
            #pragma unroll
            for (int j = 0; j < 8; j++) {
                float2 f = __half22float2(vacc[j]);
                facc[2*j]   += f.x;
                facc[2*j+1] += f.y;
                vacc[j] = __float2half2_rn(0.f);
            }
        }
    }
    #pragma unroll
    for (int j = 0; j < 8; j++) {
        float2 f = __half22float2(vacc[j]);
        facc[2*j]   += f.x;
        facc[2*j+1] += f.y;
    }
    __syncthreads();   // all reads of w/row complete; safe to reuse as reduce buffer

    // deterministic tree reduce 32 -> 1 over the dead w/row smem region
    {
        float4* rbuf = (float4*)sm->s.w;
        const int offs[5] = {0, 1024, 1536, 1792, 1920};
        const int stp[5]  = {16, 8, 4, 2, 1};
        #pragma unroll
        for (int s = 0; s < 5; s++) {
            int st = stp[s];
            if (g >= st && g < 2 * st) {
                float4* dp = rbuf + offs[s] + (g - st) * 64 + l * 4;
                dp[0] = make_float4(facc[0],  facc[1],  facc[2],  facc[3]);
                dp[1] = make_float4(facc[4],  facc[5],  facc[6],  facc[7]);
                dp[2] = make_float4(facc[8],  facc[9],  facc[10], facc[11]);
                dp[3] = make_float4(facc[12], facc[13], facc[14], facc[15]);
            }
            __syncthreads();
            if (g < st) {
                const float4* sp = rbuf + offs[s] + g * 64 + l * 4;
                float4 b0 = sp[0], b1 = sp[1], b2 = sp[2], b3 = sp[3];
                facc[0]+=b0.x;  facc[1]+=b0.y;  facc[2]+=b0.z;  facc[3]+=b0.w;
                facc[4]+=b1.x;  facc[5]+=b1.y;  facc[6]+=b1.z;  facc[7]+=b1.w;
                facc[8]+=b2.x;  facc[9]+=b2.y;  facc[10]+=b2.z; facc[11]+=b2.w;
                facc[12]+=b3.x; facc[13]+=b3.y; facc[14]+=b3.z; facc[15]+=b3.w;
            }
        }
    }
    if (g == 0) {
        const float sc = 1.0f / 1800.0f;
        *(float4*)&sm->s.agg[l*16 + 0]  = make_float4(facc[0]*sc,  facc[1]*sc,  facc[2]*sc,  facc[3]*sc);
        *(float4*)&sm->s.agg[l*16 + 4]  = make_float4(facc[4]*sc,  facc[5]*sc,  facc[6]*sc,  facc[7]*sc);
        *(float4*)&sm->s.agg[l*16 + 8]  = make_float4(facc[8]*sc,  facc[9]*sc,  facc[10]*sc, facc[11]*sc);
        *(float4*)&sm->s.agg[l*16 + 12] = make_float4(facc[12]*sc, facc[13]*sc, facc[14]*sc, facc[15]*sc);
    }
    __syncthreads();
}

// ---------------- persistent mega-kernel: 3 grid syncs per layer ----------------
__global__ void __launch_bounds__(NT, 1)
decoder_kernel(const float* __restrict__ features, const float* __restrict__ calib,
               const float* __restrict__ ego, const float* __restrict__ queries,
               const float* __restrict__ tw1, const float* __restrict__ tb1,
               const float* __restrict__ tw2, const float* __restrict__ tb2,
               const float* __restrict__ fmw1, const float* __restrict__ fmb1,
               const float* __restrict__ fmw2, const float* __restrict__ fmb2,
               const float* __restrict__ saiw, const float* __restrict__ saib,
               const float* __restrict__ saow, const float* __restrict__ saob,
               const float* __restrict__ caiw, const float* __restrict__ caib,
               const float* __restrict__ caow, const float* __restrict__ caob,
               const float* __restrict__ l1w,  const float* __restrict__ l1b,
               const float* __restrict__ l2w,  const float* __restrict__ l2b,
               const float* __restrict__ n1g,  const float* __restrict__ n1b,
               const float* __restrict__ n2g,  const float* __restrict__ n2b,
               const float* __restrict__ n3g,  const float* __restrict__ n3b,
               float* __restrict__ out)
{
    __shared__ Smem sm;
    __shared__ __align__(16) float p_qrow[256];   // post-resln1 q row (for CA q proj)
    __shared__ __align__(16) float p_qkv[512];    // CA kv staging

    int m = blockIdx.x;
    int t = threadIdx.x;
    int half = t >> 8;
    int tl   = t & 255;
    int barid = half + 1;
    SmemGemm* sg = &sm.g2.h[half];

    unsigned bar0 = 0;
    if (t == 0)
        asm volatile("ld.acquire.gpu.global.u32 %0, [%1];" : "=r"(bar0) : "l"(&g_bar_gen));
    unsigned barcnt = 0;

    // prologue: copy queries (own row only); transpose features -> fp8; weight transposes
    if (t < 256) g_q[m * 256 + t] = queries[m * 256 + t];
    {
        const int PT = PLANE / 32;                   // 320
        const int CT = CFCH / 32;                    // 8
        const int NTILE = CAMSN * TSTEP * PT * CT;   // 30720
        int tx = t & 31, ty = t >> 5;
        int pc = t & 15, pp = t >> 4;
        for (int tile = blockIdx.x; tile < NTILE; tile += NB) {
            int ct  = tile / (PT * CT);
            int rem = tile % (PT * CT);
            int p0 = (rem % PT) * 32;
            int c0 = (rem / PT) * 32;
            const float* in = features + (size_t)ct * CFCH * PLANE;
            unsigned char* op = g_feat8 + (size_t)ct * CFCH * PLANE;
            #pragma unroll
            for (int i = 0; i < 32; i += 16)
                sm.t.tile[ty + i][tx] = in[(size_t)(c0 + ty + i) * PLANE + p0 + tx];
            __syncthreads();
            {
                float lo = sm.t.tile[2 * pc + 0][pp];
                float hi = sm.t.tile[2 * pc + 1][pp];
                unsigned short v = pack8(hi, lo);
                *(unsigned short*)(op + (size_t)(p0 + pp) * CFCH + c0 + 2 * pc) = v;
            }
            __syncthreads();
        }
    }
    wtransH(&sm, fmw1, g_fmw1T, 512, 256);
    wtransH(&sm, fmw2, g_fmw2T, 256, 512);
    for (int li = 0; li < 6; li++) {
        wtransH(&sm, saow + li * 65536,  g_saowT + li * 65536,  256, 256);
        wtransH(&sm, caow + li * 65536,  g_caowT + li * 65536,  256, 256);
        wtransH(&sm, l1w  + li * 131072, g_l1wT  + li * 131072, 512, 256);
        wtransH(&sm, l2w  + li * 131072, g_l2wT  + li * 131072, 256, 512);
        wtrans32(&sm, caiw + li * 196608, g_caiwTf + li * 196608, 768, 256);
    }
    // No grid sync here: layer-0 S1 reads `queries` + input weights only;
    // the post-S1 grid sync orders all prologue writes before S2.

    for (int li = 0; li < 6; li++) {
        const float* saiw_l  = saiw + li * 768 * 256;
        const float* saib_l  = saib + li * 768;
        const float* caib_l  = caib + li * 768;
        const float* caiwT_l = g_caiwTf + li * 196608;
        const float* qsrc = (li == 0) ? queries : g_q;

        // ---- S1: GEMM: traj1 (64 tiles) + SA QKV (96 tiles), both read pre-SA q
        for (int tile = blockIdx.x * 2 + half; tile < 160; tile += 256) {
            if (tile < 64)
                gemm_tile<1,0>(sg, tl, barid, qsrc, tw1, tb1, g_h, 256, 512,
                               (tile & 7) * 16, (tile >> 3) * 64);
            else {
                int u = tile - 64;
                gemm_tile<0,1>(sg, tl, barid, qsrc, saiw_l, saib_l, nullptr, 256, 768,
                               (u & 7) * 16, (u >> 3) * 64);
            }
        }
        grid_sync(bar0, barcnt);

        // ---- S2 per-query: SA attn (+resln1, qsave->p_qrow), traj2, sampling,
        //      feature MLP (mem row stays in smem), CA kv proj -> kT2/vh2
        if (t < 256) sm.a.q[t] = g_qh[m * 256 + t];
        __syncthreads();
        attn_full(&sm, m, sm.a.q, g_kT, g_vh, g_saowT + li * 65536, saob + li * 256,
                  n1g + li * 256, n1b + li * 256, p_qrow);
        traj2_stage(&sm, m, tw2, tb2, out + li * 1408);
        sample_stage(&sm, m, calib, ego);
        mvT_256to512_h(sm.s.agg, g_fmw1T, fmb1, sm.s.h, sm.a.pbuf);
        mvT_512to256_h(sm.s.h, g_fmw2T, fmb2, sm.s.agg, sm.a.pbuf);   // mem row -> agg
        // CA K,V from mem row: cols 256..767 of caiwT (offset 64 float4)
        mvT_f<512, 256, 192, 0>(sm.s.agg, (const float4*)caiwT_l + 64, caib_l + 256,
                                p_qkv, sm.a.pbuf);
        if (t < 256) {
            g_kT2[t * NQ + m]  = p_qkv[t];
            g_vh2[m * 256 + t] = p_qkv[256 + t];
        }
        grid_sync(bar0, barcnt);

        // ---- S3 per-query: CA q proj, CA attn (+resln2, qsave->agg), FFN, resln3
        mvT_f<256, 256, 192, 0>(p_qrow, (const float4*)caiwT_l, caib_l,
                                sm.a.q, sm.a.pbuf);
        attn_full(&sm, m, sm.a.q, g_kT2, g_vh2, g_caowT + li * 65536, caob + li * 256,
                  n2g + li * 256, n2b + li * 256, sm.s.agg);
        mvT_256to512_h(sm.s.agg, g_l1wT + li * 131072, l1b + li * 512, sm.s.h, sm.a.pbuf);
        mvT_512to256_h(sm.s.h, g_l2wT + li * 131072, l2b + li * 256, sm.a.tmpv, sm.a.pbuf);
        resln_inblock(&sm, m, n3g + li * 256, n3b + li * 256, nullptr);
        grid_sync(bar0, barcnt);
    }

    // epilogue: final traj head
    for (int tile = blockIdx.x * 2 + half; tile < 64; tile += 256)
        gemm_tile<1,0>(sg, tl, barid, g_q, tw1, tb1, g_h, 256, 512,
                       (tile & 7) * 16, (tile >> 3) * 64);
    grid_sync(bar0, barcnt);
    traj2_stage(&sm, m, tw2, tb2, out + 6 * 1408);
}

// ---------------- host: one launch ----------------
extern "C" void kernel_launch(void* const* d_in, const int* in_sizes, int n_in,
                              void* d_out, int out_size)
{
    const float* features = (const float*)d_in[0];
    const float* calib    = (const float*)d_in[1];
    const float* ego      = (const float*)d_in[2];
    const float* queries  = (const float*)d_in[3];
    const float* tw1  = (const float*)d_in[5];
    const float* tb1  = (const float*)d_in[6];
    const float* tw2  = (const float*)d_in[7];
    const float* tb2  = (const float*)d_in[8];
    const float* fmw1 = (const float*)d_in[9];
    const float* fmb1 = (const float*)d_in[10];
    const float* fmw2 = (const float*)d_in[11];
    const float* fmb2 = (const float*)d_in[12];
    const float* saiw = (const float*)d_in[13];
    const float* saib = (const float*)d_in[14];
    const float* saow = (const float*)d_in[15];
    const float* saob = (const float*)d_in[16];
    const float* caiw = (const float*)d_in[17];
    const float* caib = (const float*)d_in[18];
    const float* caow = (const float*)d_in[19];
    const float* caob = (const float*)d_in[20];
    const float* l1w  = (const float*)d_in[21];
    const float* l1b  = (const float*)d_in[22];
    const float* l2w  = (const float*)d_in[23];
    const float* l2b  = (const float*)d_in[24];
    const float* n1g  = (const float*)d_in[25];
    const float* n1b  = (const float*)d_in[26];
    const float* n2g  = (const float*)d_in[27];
    const float* n2b  = (const float*)d_in[28];
    const float* n3g  = (const float*)d_in[29];
    const float* n3b  = (const float*)d_in[30];
    float* out = (float*)d_out;

    decoder_kernel<<<NB, NT>>>(features, calib, ego, queries,
                               tw1, tb1, tw2, tb2,
                               fmw1, fmb1, fmw2, fmb2,
                               saiw, saib, saow, saob,
                               caiw, caib, caow, caob,
                               l1w, l1b, l2w, l2b,
                               n1g, n1b, n2g, n2b, n3g, n3b,
                               out);
}